// round 13
// baseline (speedup 1.0000x reference)
#include <cuda_runtime.h>
#include <cuda_fp16.h>
#include <cstdint>

#define N_NODES 8192
#define IN_F    512
#define OUT_F   256

#define BM 128
#define BN 128
#define BKE 64                            // k halves per stage (128B rows)
#define NTHREADS 128
#define NSTAGE 3
#define A_TILE_BYTES 16384                // 128 rows x 128B
#define B_TILE_BYTES 16384                // 128 rows x 128B
#define STAGE_BYTES  (A_TILE_BYTES + B_TILE_BYTES)   // 32KB
#define SMEM_DYN     (NSTAGE * STAGE_BYTES)          // 96KB -> 2 CTAs/SM

#define OUT_ELEMS ((size_t)N_NODES * OUT_F)

__device__ float  g_d  [N_NODES];
__device__ __half g_Ah [(size_t)N_NODES * N_NODES];
__device__ __half g_Xh [(size_t)N_NODES * IN_F];
__device__ __half g_Wth[(size_t)OUT_F * IN_F];
__device__ __half g_Yth[(size_t)OUT_F * N_NODES];
__device__ float  g_P  [2 * OUT_ELEMS];              // split-K partials

__device__ __forceinline__ uint32_t smem_to_u32(const void* p) {
    uint32_t a;
    asm("{ .reg .u64 t; cvta.to.shared.u64 t, %1; cvt.u32.u64 %0, t; }" : "=r"(a) : "l"(p));
    return a;
}

#define SWZ(o) ((o) ^ (((o) >> 3) & 0x70))

#define CP_ASYNC_CG16(dst_u32, src_ptr) \
    asm volatile("cp.async.cg.shared.global [%0], [%1], 16;" :: "r"(dst_u32), "l"(src_ptr) : "memory")
#define CP_COMMIT()  asm volatile("cp.async.commit_group;" ::: "memory")
#define CP_WAIT1()   asm volatile("cp.async.wait_group 1;" ::: "memory")

#define LDSM_X4(r, addr) \
    asm volatile("ldmatrix.sync.aligned.m8n8.x4.shared.b16 {%0,%1,%2,%3}, [%4];" \
        : "=r"((r)[0]), "=r"((r)[1]), "=r"((r)[2]), "=r"((r)[3]) : "r"(addr))

#define MMA_F16(c, a, b0, b1) \
    asm volatile("mma.sync.aligned.m16n8k16.row.col.f32.f16.f16.f32 " \
        "{%0,%1,%2,%3}, {%4,%5,%6,%7}, {%8,%9}, {%0,%1,%2,%3};" \
        : "+f"((c)[0]), "+f"((c)[1]), "+f"((c)[2]), "+f"((c)[3]) \
        : "r"((a)[0]), "r"((a)[1]), "r"((a)[2]), "r"((a)[3]), "r"(b0), "r"(b1))

// ---------------------------------------------------------------------------
__global__ void rowsum_rsqrt_cvt_kernel(const float* __restrict__ A,
                                        float* __restrict__ d,
                                        __half* __restrict__ Ah) {
    __shared__ float red[8];
    const int row = blockIdx.x;
    const float4* a4 = reinterpret_cast<const float4*>(A + (size_t)row * N_NODES);
    uint2* o8 = reinterpret_cast<uint2*>(Ah + (size_t)row * N_NODES);
    float s = 0.0f;
#pragma unroll
    for (int i = 0; i < 8; i++) {
        float4 v = __ldcs(&a4[threadIdx.x + i * 256]);
        s += (v.x + v.y) + (v.z + v.w);
        __half2 h0 = __floats2half2_rn(v.x, v.y);
        __half2 h1 = __floats2half2_rn(v.z, v.w);
        uint2 u;
        u.x = reinterpret_cast<uint32_t&>(h0);
        u.y = reinterpret_cast<uint32_t&>(h1);
        o8[threadIdx.x + i * 256] = u;
    }
#pragma unroll
    for (int o = 16; o; o >>= 1) s += __shfl_xor_sync(0xffffffffu, s, o);
    if ((threadIdx.x & 31) == 0) red[threadIdx.x >> 5] = s;
    __syncthreads();
    if (threadIdx.x < 8) {
        float t = red[threadIdx.x];
#pragma unroll
        for (int o = 4; o; o >>= 1) t += __shfl_xor_sync(0xffu, t, o);
        if (threadIdx.x == 0) d[row] = rsqrtf(1.0f + t);
    }
}

__global__ void cvt_x_kernel(const float* __restrict__ X, __half* __restrict__ Xh) {
    const size_t i = (size_t)blockIdx.x * blockDim.x + threadIdx.x;
    float4 v = reinterpret_cast<const float4*>(X)[i];
    __half2 h0 = __floats2half2_rn(v.x, v.y);
    __half2 h1 = __floats2half2_rn(v.z, v.w);
    uint2 u;
    u.x = reinterpret_cast<uint32_t&>(h0);
    u.y = reinterpret_cast<uint32_t&>(h1);
    reinterpret_cast<uint2*>(Xh)[i] = u;
}

__global__ void transpose_cvt_w_kernel(const float* __restrict__ W, __half* __restrict__ Wt) {
    __shared__ float t[32][33];
    const int n0 = blockIdx.x * 32, k0 = blockIdx.y * 32;
    const int x = threadIdx.x, y = threadIdx.y;
#pragma unroll
    for (int j = 0; j < 32; j += 8)
        t[y + j][x] = W[(size_t)(k0 + y + j) * OUT_F + n0 + x];
    __syncthreads();
#pragma unroll
    for (int j = 0; j < 32; j += 8)
        Wt[(size_t)(n0 + y + j) * IN_F + k0 + x] = __float2half_rn(t[x][y + j]);
}

// out = p0 + p1 (split-K reduce)
__global__ void reduce2_kernel(const float* __restrict__ p, float* __restrict__ out) {
    const size_t i = (size_t)blockIdx.x * blockDim.x + threadIdx.x;
    float4 a = reinterpret_cast<const float4*>(p)[i];
    float4 b = reinterpret_cast<const float4*>(p + OUT_ELEMS)[i];
    reinterpret_cast<float4*>(out)[i] =
        make_float4(a.x + b.x, a.y + b.y, a.z + b.z, a.w + b.w);
}

// ---------------------------------------------------------------------------
// D[m,n] = sum_{k in z-slice} Aop[m,k]*Bop[n,k]; fp16 ops, fp32 acc.
// CTA 128x128, 128 threads, 4 warps 2(m)x2(n), warp tile 64x64.
// NSTAGE=3, wait_group 1, EMPTY TAIL COMMITS (race-free), 2 CTAs/SM.
// MODE 1: ((half*)Cout)[n*out_ld + m] = half(d[m]*acc)
// MODE 2: ((float*)Cout + z*OUT_ELEMS)[m*out_ld + n] = d[m]*acc
template <int MODE>
__global__ __launch_bounds__(NTHREADS, 2)
void gemm_f16_kernel(const __half* __restrict__ Aop, const __half* __restrict__ Bop,
                     void* __restrict__ Cout, const float* __restrict__ dvec,
                     int ldK, int kLen, int out_ld) {
    extern __shared__ char smem[];
    const uint32_t sbase = smem_to_u32(smem);
    const int tid = threadIdx.x;
    const int lane = tid & 31;
    const int wid = tid >> 5;
    const int wm = wid & 1;        // 2 warps in m (64 rows each)
    const int wn = wid >> 1;       // 2 warps in n (64 cols each)
    const int KT = kLen / BKE;

    // cp.async: A = 1024 chunks -> 8/thread; B same
    uint32_t sOff[8]; size_t gOff[8];
#pragma unroll
    for (int i = 0; i < 8; i++) {
        int chunk = i * NTHREADS + tid;
        int row = chunk >> 3, c = chunk & 7;
        sOff[i] = SWZ((uint32_t)(row * 128 + c * 16));
        gOff[i] = (size_t)row * ldK + (size_t)c * 8;
    }
    const size_t kOff = (size_t)blockIdx.z * (size_t)kLen;
    const __half* aP = Aop + (size_t)blockIdx.x * BM * ldK + kOff;
    const __half* bP = Bop + (size_t)blockIdx.y * BN * ldK + kOff;

    auto load_tile = [&](int kt, int slot) {
        const uint32_t base = sbase + (uint32_t)slot * STAGE_BYTES;
        const __half* a = aP + (size_t)kt * BKE;
        const __half* b = bP + (size_t)kt * BKE;
#pragma unroll
        for (int i = 0; i < 8; i++) CP_ASYNC_CG16(base + sOff[i], a + gOff[i]);
#pragma unroll
        for (int i = 0; i < 8; i++) CP_ASYNC_CG16(base + A_TILE_BYTES + sOff[i], b + gOff[i]);
        CP_COMMIT();
    };

    // ldmatrix addresses
    uint32_t aRow[4], aX[4];
    const uint32_t aK = ((lane >> 4) & 1) * 16;
#pragma unroll
    for (int f = 0; f < 4; f++) {
        int m = wm * 64 + f * 16 + (lane & 7) + ((lane >> 3) & 1) * 8;
        aRow[f] = (uint32_t)(m * 128);
        aX[f]   = (uint32_t)((m & 7) << 4);
    }
    uint32_t bRow[4], bX[4];
    const uint32_t bK = ((lane >> 3) & 1) * 16;
#pragma unroll
    for (int g = 0; g < 4; g++) {
        int n = wn * 64 + g * 16 + ((lane >> 4) & 1) * 8 + (lane & 7);
        bRow[g] = (uint32_t)(A_TILE_BYTES + n * 128);
        bX[g]   = (uint32_t)((n & 7) << 4);
    }

    float acc[4][8][4];
#pragma unroll
    for (int i = 0; i < 4; i++)
#pragma unroll
        for (int j = 0; j < 8; j++)
#pragma unroll
            for (int r = 0; r < 4; r++) acc[i][j][r] = 0.0f;

    // prologue: 2 stages
    load_tile(0, 0);
    load_tile(1, 1);

    int cslot = 0, pslot = 2;
    for (int k = 0; k < KT; k++) {
        CP_WAIT1();
        __syncthreads();
        const int kn = k + NSTAGE - 1;
        if (kn < KT) {
            load_tile(kn, pslot);
            if (++pslot == NSTAGE) pslot = 0;
        } else {
            CP_COMMIT();               // empty tail commit: keeps wait_group sound
        }

        const uint32_t stage = sbase + (uint32_t)cslot * STAGE_BYTES;
        if (++cslot == NSTAGE) cslot = 0;
#pragma unroll
        for (int ks = 0; ks < 4; ks++) {
            uint32_t af[4][4], bf[4][4];
            const uint32_t kb = (uint32_t)(ks * 32);
#pragma unroll
            for (int f = 0; f < 4; f++)
                LDSM_X4(af[f], stage + aRow[f] + ((kb + aK) ^ aX[f]));
#pragma unroll
            for (int g = 0; g < 4; g++)
                LDSM_X4(bf[g], stage + bRow[g] + ((kb + bK) ^ bX[g]));
#pragma unroll
            for (int mf = 0; mf < 4; mf++)
#pragma unroll
                for (int nf = 0; nf < 8; nf++)
                    MMA_F16(acc[mf][nf], af[mf], bf[nf >> 1][(nf & 1) * 2],
                            bf[nf >> 1][(nf & 1) * 2 + 1]);
        }
    }

    const int mBase = blockIdx.x * BM + wm * 64;
    const int nBase = blockIdx.y * BN + wn * 64;
#pragma unroll
    for (int mf = 0; mf < 4; mf++) {
        const int m0 = mBase + mf * 16 + (lane >> 2);
        const float d0 = dvec[m0];
        const float d8 = dvec[m0 + 8];
#pragma unroll
        for (int nf = 0; nf < 8; nf++) {
            const int n = nBase + nf * 8 + (lane & 3) * 2;
            if (MODE == 1) {
                __half* C = reinterpret_cast<__half*>(Cout);
                C[(size_t)n       * out_ld + m0    ] = __float2half_rn(d0 * acc[mf][nf][0]);
                C[(size_t)(n + 1) * out_ld + m0    ] = __float2half_rn(d0 * acc[mf][nf][1]);
                C[(size_t)n       * out_ld + m0 + 8] = __float2half_rn(d8 * acc[mf][nf][2]);
                C[(size_t)(n + 1) * out_ld + m0 + 8] = __float2half_rn(d8 * acc[mf][nf][3]);
            } else {
                float* C = reinterpret_cast<float*>(Cout) + (size_t)blockIdx.z * OUT_ELEMS;
                float2 v0 = make_float2(d0 * acc[mf][nf][0], d0 * acc[mf][nf][1]);
                float2 v1 = make_float2(d8 * acc[mf][nf][2], d8 * acc[mf][nf][3]);
                *reinterpret_cast<float2*>(&C[(size_t)m0       * out_ld + n]) = v0;
                *reinterpret_cast<float2*>(&C[(size_t)(m0 + 8) * out_ld + n]) = v1;
            }
        }
    }
}

// ---------------------------------------------------------------------------
extern "C" void kernel_launch(void* const* d_in, const int* in_sizes, int n_in,
                              void* d_out, int out_size) {
    const float* A = (const float*)d_in[0];
    const float* X = (const float*)d_in[1];
    const float* W = (const float*)d_in[2];
    float* out = (float*)d_out;
    (void)in_sizes; (void)n_in; (void)out_size;

    float *dv, *P;
    __half *Ah, *Xh, *Wth, *Yth;
    cudaGetSymbolAddress((void**)&dv,  g_d);
    cudaGetSymbolAddress((void**)&P,   g_P);
    cudaGetSymbolAddress((void**)&Ah,  g_Ah);
    cudaGetSymbolAddress((void**)&Xh,  g_Xh);
    cudaGetSymbolAddress((void**)&Wth, g_Wth);
    cudaGetSymbolAddress((void**)&Yth, g_Yth);

    cudaFuncSetAttribute(gemm_f16_kernel<1>,
                         cudaFuncAttributeMaxDynamicSharedMemorySize, SMEM_DYN);
    cudaFuncSetAttribute(gemm_f16_kernel<2>,
                         cudaFuncAttributeMaxDynamicSharedMemorySize, SMEM_DYN);

    rowsum_rsqrt_cvt_kernel<<<N_NODES, 256>>>(A, dv, Ah);
    cvt_x_kernel<<<(N_NODES * IN_F) / (256 * 4), 256>>>(X, Xh);
    transpose_cvt_w_kernel<<<dim3(OUT_F / 32, IN_F / 32), dim3(32, 8)>>>(W, Wth);

    // GEMM1: Yth[n][m] = fp16( d[m] * sum_k Xh[m][k] * Wth[n][k] )
    gemm_f16_kernel<1><<<dim3(N_NODES / BM, OUT_F / BN, 1), NTHREADS, SMEM_DYN>>>(
        Xh, Wth, (void*)Yth, dv, IN_F, IN_F, N_NODES);

    // GEMM2 split-K=2: P[z][m][n] = d[m] * sum_{j in half z} Ah[m][j]*Yth[n][j]
    gemm_f16_kernel<2><<<dim3(N_NODES / BM, OUT_F / BN, 2), NTHREADS, SMEM_DYN>>>(
        Ah, Yth, (void*)P, dv, N_NODES, N_NODES / 2, OUT_F);

    // out = P[0] + P[1]
    reduce2_kernel<<<(int)(OUT_ELEMS / (256 * 4)), 256>>>(P, out);
}

// round 14
// speedup vs baseline: 1.0054x; 1.0054x over previous
#include <cuda_runtime.h>
#include <cuda_fp16.h>
#include <cstdint>

#define N_NODES 8192
#define IN_F    512
#define OUT_F   256

#define BM 128
#define BN 128
#define BKE 64                            // k halves per stage (128B rows)
#define NTHREADS 128
#define NSTAGE 3
#define A_TILE_BYTES 16384                // 128 rows x 128B
#define B_TILE_BYTES 16384                // 128 rows x 128B
#define STAGE_BYTES  (A_TILE_BYTES + B_TILE_BYTES)   // 32KB
#define SMEM_DYN     (NSTAGE * STAGE_BYTES)          // 96KB -> 2 CTAs/SM

#define OUT_ELEMS ((size_t)N_NODES * OUT_F)

__device__ float  g_d  [N_NODES];
__device__ __half g_Ah [(size_t)N_NODES * N_NODES];
__device__ __half g_Xh [(size_t)N_NODES * IN_F];
__device__ __half g_Wth[(size_t)OUT_F * IN_F];
__device__ __half g_Yth[(size_t)OUT_F * N_NODES];
__device__ float  g_P  [2 * OUT_ELEMS];              // split-K partials

__device__ __forceinline__ uint32_t smem_to_u32(const void* p) {
    uint32_t a;
    asm("{ .reg .u64 t; cvta.to.shared.u64 t, %1; cvt.u32.u64 %0, t; }" : "=r"(a) : "l"(p));
    return a;
}

#define SWZ(o) ((o) ^ (((o) >> 3) & 0x70))

#define CP_ASYNC_CG16(dst_u32, src_ptr) \
    asm volatile("cp.async.cg.shared.global [%0], [%1], 16;" :: "r"(dst_u32), "l"(src_ptr) : "memory")
#define CP_COMMIT()  asm volatile("cp.async.commit_group;" ::: "memory")
#define CP_WAIT1()   asm volatile("cp.async.wait_group 1;" ::: "memory")

#define LDSM_X4(r, addr) \
    asm volatile("ldmatrix.sync.aligned.m8n8.x4.shared.b16 {%0,%1,%2,%3}, [%4];" \
        : "=r"((r)[0]), "=r"((r)[1]), "=r"((r)[2]), "=r"((r)[3]) : "r"(addr))

#define MMA_F16(c, a, b0, b1) \
    asm volatile("mma.sync.aligned.m16n8k16.row.col.f32.f16.f16.f32 " \
        "{%0,%1,%2,%3}, {%4,%5,%6,%7}, {%8,%9}, {%0,%1,%2,%3};" \
        : "+f"((c)[0]), "+f"((c)[1]), "+f"((c)[2]), "+f"((c)[3]) \
        : "r"((a)[0]), "r"((a)[1]), "r"((a)[2]), "r"((a)[3]), "r"(b0), "r"(b1))

// ---------------------------------------------------------------------------
__global__ void rowsum_rsqrt_cvt_kernel(const float* __restrict__ A,
                                        float* __restrict__ d,
                                        __half* __restrict__ Ah) {
    __shared__ float red[8];
    const int row = blockIdx.x;
    const float4* a4 = reinterpret_cast<const float4*>(A + (size_t)row * N_NODES);
    uint2* o8 = reinterpret_cast<uint2*>(Ah + (size_t)row * N_NODES);
    float s = 0.0f;
#pragma unroll
    for (int i = 0; i < 8; i++) {
        float4 v = __ldcs(&a4[threadIdx.x + i * 256]);
        s += (v.x + v.y) + (v.z + v.w);
        __half2 h0 = __floats2half2_rn(v.x, v.y);
        __half2 h1 = __floats2half2_rn(v.z, v.w);
        uint2 u;
        u.x = reinterpret_cast<uint32_t&>(h0);
        u.y = reinterpret_cast<uint32_t&>(h1);
        o8[threadIdx.x + i * 256] = u;
    }
#pragma unroll
    for (int o = 16; o; o >>= 1) s += __shfl_xor_sync(0xffffffffu, s, o);
    if ((threadIdx.x & 31) == 0) red[threadIdx.x >> 5] = s;
    __syncthreads();
    if (threadIdx.x < 8) {
        float t = red[threadIdx.x];
#pragma unroll
        for (int o = 4; o; o >>= 1) t += __shfl_xor_sync(0xffu, t, o);
        if (threadIdx.x == 0) d[row] = rsqrtf(1.0f + t);
    }
}

__global__ void cvt_x_kernel(const float* __restrict__ X, __half* __restrict__ Xh) {
    const size_t i = (size_t)blockIdx.x * blockDim.x + threadIdx.x;
    float4 v = reinterpret_cast<const float4*>(X)[i];
    __half2 h0 = __floats2half2_rn(v.x, v.y);
    __half2 h1 = __floats2half2_rn(v.z, v.w);
    uint2 u;
    u.x = reinterpret_cast<uint32_t&>(h0);
    u.y = reinterpret_cast<uint32_t&>(h1);
    reinterpret_cast<uint2*>(Xh)[i] = u;
}

__global__ void transpose_cvt_w_kernel(const float* __restrict__ W, __half* __restrict__ Wt) {
    __shared__ float t[32][33];
    const int n0 = blockIdx.x * 32, k0 = blockIdx.y * 32;
    const int x = threadIdx.x, y = threadIdx.y;
#pragma unroll
    for (int j = 0; j < 32; j += 8)
        t[y + j][x] = W[(size_t)(k0 + y + j) * OUT_F + n0 + x];
    __syncthreads();
#pragma unroll
    for (int j = 0; j < 32; j += 8)
        Wt[(size_t)(n0 + y + j) * IN_F + k0 + x] = __float2half_rn(t[x][y + j]);
}

// out = p0 + p1 (split-K reduce)
__global__ void reduce2_kernel(const float* __restrict__ p, float* __restrict__ out) {
    const size_t i = (size_t)blockIdx.x * blockDim.x + threadIdx.x;
    float4 a = reinterpret_cast<const float4*>(p)[i];
    float4 b = reinterpret_cast<const float4*>(p + OUT_ELEMS)[i];
    reinterpret_cast<float4*>(out)[i] =
        make_float4(a.x + b.x, a.y + b.y, a.z + b.z, a.w + b.w);
}

// ---------------------------------------------------------------------------
// D[m,n] = sum_{k in z-slice} Aop[m,k]*Bop[n,k]; fp16 ops, fp32 acc.
// CTA 128x128, 128 threads, 4 warps 2(m)x2(n), warp tile 64x64.
// NSTAGE=3, wait_group 1, EMPTY TAIL COMMITS (race-free), 2 CTAs/SM.
// MODE 1: ((half*)Cout)[n*out_ld + m] = half(d[m]*acc)
// MODE 2: ((float*)Cout + z*OUT_ELEMS)[m*out_ld + n] = d[m]*acc
template <int MODE>
__global__ __launch_bounds__(NTHREADS, 2)
void gemm_f16_kernel(const __half* __restrict__ Aop, const __half* __restrict__ Bop,
                     void* __restrict__ Cout, const float* __restrict__ dvec,
                     int ldK, int kLen, int out_ld) {
    extern __shared__ char smem[];
    const uint32_t sbase = smem_to_u32(smem);
    const int tid = threadIdx.x;
    const int lane = tid & 31;
    const int wid = tid >> 5;
    const int wm = wid & 1;        // 2 warps in m (64 rows each)
    const int wn = wid >> 1;       // 2 warps in n (64 cols each)
    const int KT = kLen / BKE;

    // cp.async: A = 1024 chunks -> 8/thread; B same
    uint32_t sOff[8]; size_t gOff[8];
#pragma unroll
    for (int i = 0; i < 8; i++) {
        int chunk = i * NTHREADS + tid;
        int row = chunk >> 3, c = chunk & 7;
        sOff[i] = SWZ((uint32_t)(row * 128 + c * 16));
        gOff[i] = (size_t)row * ldK + (size_t)c * 8;
    }
    const size_t kOff = (size_t)blockIdx.z * (size_t)kLen;
    const __half* aP = Aop + (size_t)blockIdx.x * BM * ldK + kOff;
    const __half* bP = Bop + (size_t)blockIdx.y * BN * ldK + kOff;

    auto load_tile = [&](int kt, int slot) {
        const uint32_t base = sbase + (uint32_t)slot * STAGE_BYTES;
        const __half* a = aP + (size_t)kt * BKE;
        const __half* b = bP + (size_t)kt * BKE;
#pragma unroll
        for (int i = 0; i < 8; i++) CP_ASYNC_CG16(base + sOff[i], a + gOff[i]);
#pragma unroll
        for (int i = 0; i < 8; i++) CP_ASYNC_CG16(base + A_TILE_BYTES + sOff[i], b + gOff[i]);
        CP_COMMIT();
    };

    // ldmatrix addresses
    uint32_t aRow[4], aX[4];
    const uint32_t aK = ((lane >> 4) & 1) * 16;
#pragma unroll
    for (int f = 0; f < 4; f++) {
        int m = wm * 64 + f * 16 + (lane & 7) + ((lane >> 3) & 1) * 8;
        aRow[f] = (uint32_t)(m * 128);
        aX[f]   = (uint32_t)((m & 7) << 4);
    }
    uint32_t bRow[4], bX[4];
    const uint32_t bK = ((lane >> 3) & 1) * 16;
#pragma unroll
    for (int g = 0; g < 4; g++) {
        int n = wn * 64 + g * 16 + ((lane >> 4) & 1) * 8 + (lane & 7);
        bRow[g] = (uint32_t)(A_TILE_BYTES + n * 128);
        bX[g]   = (uint32_t)((n & 7) << 4);
    }

    float acc[4][8][4];
#pragma unroll
    for (int i = 0; i < 4; i++)
#pragma unroll
        for (int j = 0; j < 8; j++)
#pragma unroll
            for (int r = 0; r < 4; r++) acc[i][j][r] = 0.0f;

    // prologue: 2 stages
    load_tile(0, 0);
    load_tile(1, 1);

    int cslot = 0, pslot = 2;
    for (int k = 0; k < KT; k++) {
        CP_WAIT1();
        __syncthreads();
        const int kn = k + NSTAGE - 1;
        if (kn < KT) {
            load_tile(kn, pslot);
            if (++pslot == NSTAGE) pslot = 0;
        } else {
            CP_COMMIT();               // empty tail commit: keeps wait_group sound
        }

        const uint32_t stage = sbase + (uint32_t)cslot * STAGE_BYTES;
        if (++cslot == NSTAGE) cslot = 0;
#pragma unroll
        for (int ks = 0; ks < 4; ks++) {
            uint32_t af[4][4], bf[4][4];
            const uint32_t kb = (uint32_t)(ks * 32);
#pragma unroll
            for (int f = 0; f < 4; f++)
                LDSM_X4(af[f], stage + aRow[f] + ((kb + aK) ^ aX[f]));
#pragma unroll
            for (int g = 0; g < 4; g++)
                LDSM_X4(bf[g], stage + bRow[g] + ((kb + bK) ^ bX[g]));
#pragma unroll
            for (int mf = 0; mf < 4; mf++)
#pragma unroll
                for (int nf = 0; nf < 8; nf++)
                    MMA_F16(acc[mf][nf], af[mf], bf[nf >> 1][(nf & 1) * 2],
                            bf[nf >> 1][(nf & 1) * 2 + 1]);
        }
    }

    const int mBase = blockIdx.x * BM + wm * 64;
    const int nBase = blockIdx.y * BN + wn * 64;
#pragma unroll
    for (int mf = 0; mf < 4; mf++) {
        const int m0 = mBase + mf * 16 + (lane >> 2);
        const float d0 = dvec[m0];
        const float d8 = dvec[m0 + 8];
#pragma unroll
        for (int nf = 0; nf < 8; nf++) {
            const int n = nBase + nf * 8 + (lane & 3) * 2;
            if (MODE == 1) {
                __half* C = reinterpret_cast<__half*>(Cout);
                C[(size_t)n       * out_ld + m0    ] = __float2half_rn(d0 * acc[mf][nf][0]);
                C[(size_t)(n + 1) * out_ld + m0    ] = __float2half_rn(d0 * acc[mf][nf][1]);
                C[(size_t)n       * out_ld + m0 + 8] = __float2half_rn(d8 * acc[mf][nf][2]);
                C[(size_t)(n + 1) * out_ld + m0 + 8] = __float2half_rn(d8 * acc[mf][nf][3]);
            } else {
                float* C = reinterpret_cast<float*>(Cout) + (size_t)blockIdx.z * OUT_ELEMS;
                float2 v0 = make_float2(d0 * acc[mf][nf][0], d0 * acc[mf][nf][1]);
                float2 v1 = make_float2(d8 * acc[mf][nf][2], d8 * acc[mf][nf][3]);
                *reinterpret_cast<float2*>(&C[(size_t)m0       * out_ld + n]) = v0;
                *reinterpret_cast<float2*>(&C[(size_t)(m0 + 8) * out_ld + n]) = v1;
            }
        }
    }
}

// ---------------------------------------------------------------------------
extern "C" void kernel_launch(void* const* d_in, const int* in_sizes, int n_in,
                              void* d_out, int out_size) {
    const float* A = (const float*)d_in[0];
    const float* X = (const float*)d_in[1];
    const float* W = (const float*)d_in[2];
    float* out = (float*)d_out;
    (void)in_sizes; (void)n_in; (void)out_size;

    float *dv, *P;
    __half *Ah, *Xh, *Wth, *Yth;
    cudaGetSymbolAddress((void**)&dv,  g_d);
    cudaGetSymbolAddress((void**)&P,   g_P);
    cudaGetSymbolAddress((void**)&Ah,  g_Ah);
    cudaGetSymbolAddress((void**)&Xh,  g_Xh);
    cudaGetSymbolAddress((void**)&Wth, g_Wth);
    cudaGetSymbolAddress((void**)&Yth, g_Yth);

    cudaFuncSetAttribute(gemm_f16_kernel<1>,
                         cudaFuncAttributeMaxDynamicSharedMemorySize, SMEM_DYN);
    cudaFuncSetAttribute(gemm_f16_kernel<2>,
                         cudaFuncAttributeMaxDynamicSharedMemorySize, SMEM_DYN);

    rowsum_rsqrt_cvt_kernel<<<N_NODES, 256>>>(A, dv, Ah);
    cvt_x_kernel<<<(N_NODES * IN_F) / (256 * 4), 256>>>(X, Xh);
    transpose_cvt_w_kernel<<<dim3(OUT_F / 32, IN_F / 32), dim3(32, 8)>>>(W, Wth);

    // GEMM1: Yth[n][m] = fp16( d[m] * sum_k Xh[m][k] * Wth[n][k] )
    gemm_f16_kernel<1><<<dim3(N_NODES / BM, OUT_F / BN, 1), NTHREADS, SMEM_DYN>>>(
        Xh, Wth, (void*)Yth, dv, IN_F, IN_F, N_NODES);

    // GEMM2 split-K=2: P[z][m][n] = d[m] * sum_{j in half z} Ah[m][j]*Yth[n][j]
    gemm_f16_kernel<2><<<dim3(N_NODES / BM, OUT_F / BN, 2), NTHREADS, SMEM_DYN>>>(
        Ah, Yth, (void*)P, dv, N_NODES, N_NODES / 2, OUT_F);

    // out = P[0] + P[1]
    reduce2_kernel<<<(int)(OUT_ELEMS / (256 * 4)), 256>>>(P, out);
}